// round 15
// baseline (speedup 1.0000x reference)
#include <cuda_runtime.h>
#include <cuda_bf16.h>
#include <cuda_fp16.h>
#include <cstdint>

#define NT   8192
#define DD   1024
#define GHA  512
#define GHB  256
#define NE   8
#define HH   2048
#define MAX_MTILES 136

typedef __nv_bfloat16 bf16;

// ---------------- scratch ---------------------------------------------------
__device__ bf16  g_xhi[NT * DD],  g_xlo[NT * DD];
__device__ bf16  g_h1hi[NT * GHA], g_h1lo[NT * GHA];
__device__ bf16  g_w1hi[GHA * DD], g_w1lo[GHA * DD];
__device__ bf16  g_w2hi[GHB * GHA], g_w2lo[GHB * GHA];
__device__ __half g_xh[NT * DD];
__device__ __half g_ewh[(size_t)NE * HH * DD];             // [E][H][D]
__device__ __half g_owh[(size_t)DD * HH];                  // [D][H]
__device__ __half g_pairh[(size_t)NT * 2 * HH];
__device__ float g_logit[NT * NE];
__device__ float g_tb3[3 * NE];
__device__ float g_wval[NT * 2];
__device__ int   g_cnt[NE];
__device__ int   g_list[NE * NT];

// ---------------- PTX helpers (sm_80+ baseline only) ------------------------
__device__ __forceinline__ uint32_t smem_u32(const void* p) {
    uint32_t a;
    asm("{ .reg .u64 t; cvta.to.shared.u64 t, %1; cvt.u32.u64 %0, t; }" : "=r"(a) : "l"(p));
    return a;
}
__device__ __forceinline__ void cp16(uint32_t s, const void* g) {
    asm volatile("cp.async.cg.shared.global [%0], [%1], 16;" :: "r"(s), "l"(g));
}
#define CP_COMMIT() asm volatile("cp.async.commit_group;" ::: "memory")
#define CP_WAIT1()  asm volatile("cp.async.wait_group 1;" ::: "memory")
#define CP_WAIT0()  asm volatile("cp.async.wait_group 0;" ::: "memory")

__device__ __forceinline__ void ldsm_x4(uint32_t* r, uint32_t a) {
    asm volatile("ldmatrix.sync.aligned.m8n8.x4.shared.b16 {%0,%1,%2,%3}, [%4];"
        : "=r"(r[0]), "=r"(r[1]), "=r"(r[2]), "=r"(r[3]) : "r"(a));
}
__device__ __forceinline__ void mma_bf16(float* c, const uint32_t* a, const uint32_t* b) {
    asm volatile("mma.sync.aligned.m16n8k16.row.col.f32.bf16.bf16.f32 "
        "{%0,%1,%2,%3}, {%4,%5,%6,%7}, {%8,%9}, {%0,%1,%2,%3};"
        : "+f"(c[0]), "+f"(c[1]), "+f"(c[2]), "+f"(c[3])
        : "r"(a[0]), "r"(a[1]), "r"(a[2]), "r"(a[3]), "r"(b[0]), "r"(b[1]));
}
__device__ __forceinline__ void mma_f16(float* c, const uint32_t* a, const uint32_t* b) {
    asm volatile("mma.sync.aligned.m16n8k16.row.col.f32.f16.f16.f32 "
        "{%0,%1,%2,%3}, {%4,%5,%6,%7}, {%8,%9}, {%0,%1,%2,%3};"
        : "+f"(c[0]), "+f"(c[1]), "+f"(c[2]), "+f"(c[3])
        : "r"(a[0]), "r"(a[1]), "r"(a[2]), "r"(a[3]), "r"(b[0]), "r"(b[1]));
}

// combine 8 halves: relu(w0*a + w1*b) -> fp16 (identical math to old combine)
__device__ __forceinline__ uint4 comb16s(uint4 a, uint4 b, float w0, float w1) {
    uint4 o;
    const uint32_t* ap = (const uint32_t*)&a;
    const uint32_t* bp = (const uint32_t*)&b;
    __half2* op = (__half2*)&o;
    #pragma unroll
    for (int i = 0; i < 4; i++) {
        float2 fa = __half22float2(*(const __half2*)&ap[i]);
        float2 fb = __half22float2(*(const __half2*)&bp[i]);
        float v0 = fmaxf(fmaf(w0, fa.x, w1 * fb.x), 0.f);
        float v1 = fmaxf(fmaf(w0, fa.y, w1 * fb.y), 0.f);
        op[i] = __floats2half2_rn(v0, v1);
    }
    return o;
}

// ---------------- fused prep kernel ------------------------------------------
#define PREP_BLOCKS 27265

__global__ void __launch_bounds__(256) prep_kernel(
    const float* __restrict__ x, const float* __restrict__ gw1,
    const float* __restrict__ gw2, const float* __restrict__ ew,
    const float* __restrict__ ow,
    const float* __restrict__ gb3, const float* __restrict__ temb,
    const float* __restrict__ tw, const float* __restrict__ tb) {
    __shared__ float t[32][33];
    int b = blockIdx.x;
    const int tid = threadIdx.x;

    if (b == PREP_BLOCKS - 1) {
        if (tid < 192) {
            const int p = tid >> 3;
            const int s = tid & 7;
            const int ty = p / NE, e = p % NE;
            float sum = 0.f;
            #pragma unroll
            for (int k = 0; k < 16; k++) {
                int j = s + (k << 3);
                sum += temb[ty * 128 + j] * tw[j * NE + e];
            }
            #pragma unroll
            for (int off = 4; off; off >>= 1)
                sum += __shfl_down_sync(0xffffffffu, sum, off);
            if (s == 0) g_tb3[p] = sum + gb3[e] + tb[e];
        }
        return;
    }

    if (b < 8192) {
        if (b == 0 && tid < NE) g_cnt[tid] = 0;
        if (b < 64) {
            ((float4*)g_logit)[b * 256 + tid] = make_float4(0.f, 0.f, 0.f, 0.f);
        }
        int i4 = b * 256 + tid;
        float4 v = ((const float4*)x)[i4];
        float f[4] = {v.x, v.y, v.z, v.w};
        bf16 bh[4]; bf16 bl[4]; __half hh[4];
        #pragma unroll
        for (int k = 0; k < 4; k++) {
            bh[k] = __float2bfloat16(f[k]);
            bl[k] = __float2bfloat16(f[k] - __bfloat162float(bh[k]));
            hh[k] = __float2half(f[k]);
        }
        __nv_bfloat162* xhi2 = (__nv_bfloat162*)g_xhi;
        __nv_bfloat162* xlo2 = (__nv_bfloat162*)g_xlo;
        __half2* xh2 = (__half2*)g_xh;
        xhi2[2 * i4 + 0] = __nv_bfloat162(bh[0], bh[1]);
        xhi2[2 * i4 + 1] = __nv_bfloat162(bh[2], bh[3]);
        xlo2[2 * i4 + 0] = __nv_bfloat162(bl[0], bl[1]);
        xlo2[2 * i4 + 1] = __nv_bfloat162(bl[2], bl[3]);
        xh2[2 * i4 + 0] = __half2(hh[0], hh[1]);
        xh2[2 * i4 + 1] = __half2(hh[2], hh[3]);
        return;
    }
    b -= 8192;

    const float* in;
    bf16 *ohi = nullptr, *olo = nullptr;
    __half* oh = nullptr;
    int R, C, bx, by;
    size_t zoff = 0;
    bool half_mode;
    if (b < 512) {
        half_mode = false; in = gw1; ohi = g_w1hi; olo = g_w1lo;
        R = DD; C = GHA; bx = b % 16; by = b / 16;
    } else if (b < 640) {
        b -= 512;
        half_mode = false; in = gw2; ohi = g_w2hi; olo = g_w2lo;
        R = GHA; C = GHB; bx = b % 8; by = b / 8;
    } else if (b < 640 + 16384) {
        b -= 640;
        half_mode = true; in = ew; oh = g_ewh;
        R = DD; C = HH; bx = b % 64; by = (b / 64) % 32;
        zoff = (size_t)(b / (64 * 32)) * R * C;
    } else {
        b -= 640 + 16384;
        half_mode = true; in = ow; oh = g_owh;
        R = HH; C = DD; bx = b % 32; by = b / 32;
    }
    in += zoff;
    const int c0 = bx * 32, r0 = by * 32;
    const int tx = tid & 31, ty = tid >> 5;
    for (int i = ty; i < 32; i += 8)
        t[i][tx] = in[(size_t)(r0 + i) * C + c0 + tx];
    __syncthreads();
    if (half_mode) {
        oh += zoff;
        for (int i = ty; i < 32; i += 8)
            oh[(size_t)(c0 + i) * R + r0 + tx] = __float2half(t[tx][i]);
    } else {
        for (int i = ty; i < 32; i += 8) {
            float v = t[tx][i];
            bf16 h = __float2bfloat16(v);
            size_t o = (size_t)(c0 + i) * R + r0 + tx;
            ohi[o] = h;
            olo[o] = __float2bfloat16(v - __bfloat162float(h));
        }
    }
}

// ---------------- routing: two-level atomics ---------------------------------
__global__ void __launch_bounds__(256) routing_kernel(const int* __restrict__ ftypes) {
    __shared__ float s_tb3[3 * NE];
    __shared__ int s_cnt[NE];
    __shared__ int s_base[NE];
    const int tid = threadIdx.x;
    if (tid < 3 * NE) s_tb3[tid] = g_tb3[tid];
    if (tid < NE) s_cnt[tid] = 0;
    __syncthreads();
    const int t = blockIdx.x * 256 + tid;
    float4 l0 = ((const float4*)g_logit)[t * 2 + 0];
    float4 l1 = ((const float4*)g_logit)[t * 2 + 1];
    float logits[NE] = {l0.x, l0.y, l0.z, l0.w, l1.x, l1.y, l1.z, l1.w};
    int ftv = ftypes[t];
    #pragma unroll
    for (int e = 0; e < NE; e++) logits[e] += s_tb3[ftv * NE + e];
    int i0 = 0;
    #pragma unroll
    for (int e = 1; e < NE; e++) if (logits[e] > logits[i0]) i0 = e;
    int i1 = (i0 == 0) ? 1 : 0;
    #pragma unroll
    for (int e = 0; e < NE; e++) {
        if (e == i0 || e == i1) continue;
        if (logits[e] > logits[i1]) i1 = e;
    }
    float r = expf(logits[i1] - logits[i0]);
    float inv = 1.f / (1.f + r);
    g_wval[t * 2 + 0] = inv;
    g_wval[t * 2 + 1] = r * inv;
    int p0 = atomicAdd(&s_cnt[i0], 1);
    int p1 = atomicAdd(&s_cnt[i1], 1);
    __syncthreads();
    if (tid < NE) s_base[tid] = atomicAdd(&g_cnt[tid], s_cnt[tid]);
    __syncthreads();
    g_list[i0 * NT + s_base[i0] + p0] = t * 2 + 0;
    g_list[i1 * NT + s_base[i1] + p1] = t * 2 + 1;
}

// ================= bf16 3-term GEMM (gating), 2-stage, occ 2 =================
#define EPI_RELU_SPLIT 0
#define EPI_GATE       1

#define ROWB      80
#define TILES_OFF 2048
#define STAGE_SZ  40960
#define OA_HI 0
#define OA_LO 10240
#define OB_HI 20480
#define OB_LO 30720
#define GATE_OFF  (TILES_OFF + 2 * STAGE_SZ)
#define SMEM_GEMM GATE_OFF                       // 83968
#define SMEM_GATE (GATE_OFF + GHB * NE * 4)      // 92160

template<int MODE>
__global__ void __launch_bounds__(512, 2) mma_gemm(
    const bf16* __restrict__ Ahi, const bf16* __restrict__ Alo,
    const bf16* __restrict__ Bhi, const bf16* __restrict__ Blo,
    const float* __restrict__ bias, const float* __restrict__ gw3,
    bf16* __restrict__ outhi, bf16* __restrict__ outlo,
    int N, int K) {
    extern __shared__ char smem[];
    const int tid = threadIdx.x, lane = tid & 31, wid = tid >> 5;
    const int wm = wid >> 2, wn = wid & 3;
    const int nb = blockIdx.x;
    const int mtile = blockIdx.y;

    float* s_g3 = (float*)(smem + GATE_OFF);
    if (MODE == EPI_GATE) {
        for (int i = tid; i < GHB * NE; i += 512) s_g3[i] = gw3[i];
    }

    const uint32_t sb = smem_u32(smem) + TILES_OFF;

    const int seg = tid & 3;
    const int row = tid >> 2;
    size_t arow = (size_t)mtile * 128 + row;
    size_t brow = (size_t)nb * 128 + row;
    const bf16* pAh = Ahi + arow * K + seg * 8;
    const bf16* pAl = Alo + arow * K + seg * 8;
    const bf16* pBh = Bhi + brow * K + seg * 8;
    const bf16* pBl = Blo + brow * K + seg * 8;
    const uint32_t so = row * ROWB + seg * 16;

    float acc[2][4][4] = {};
    const int niter = K >> 5;

    {
        cp16(sb + OA_HI + so, pAh);
        cp16(sb + OA_LO + so, pAl);
        cp16(sb + OB_HI + so, pBh);
        cp16(sb + OB_LO + so, pBl);
        CP_COMMIT();
    }

    for (int it = 0; it < niter; it++) {
        CP_WAIT0();
        __syncthreads();
        {
            const int s = it + 1;
            if (s < niter) {
                const uint32_t st = sb + (s & 1) * STAGE_SZ;
                const int ko = s << 5;
                cp16(st + OA_HI + so, pAh + ko);
                cp16(st + OA_LO + so, pAl + ko);
                cp16(st + OB_HI + so, pBh + ko);
                cp16(st + OB_LO + so, pBl + ko);
            }
            CP_COMMIT();
        }

        const uint32_t st = sb + (it & 1) * STAGE_SZ;
        #pragma unroll
        for (int ks = 0; ks < 2; ks++) {
            uint32_t ah[2][4], al[2][4], bx[2][4];
            const int acol = (ks * 16 + (lane >> 4) * 8) * 2;
            #pragma unroll
            for (int mt = 0; mt < 2; mt++) {
                uint32_t ad = st + (wm * 32 + mt * 16 + (lane & 15)) * ROWB + acol;
                ldsm_x4(ah[mt], ad + OA_HI);
                ldsm_x4(al[mt], ad + OA_LO);
            }
            const int bcol = (ks * 16 + ((lane >> 3) & 1) * 8) * 2;
            #pragma unroll
            for (int pr = 0; pr < 2; pr++) {
                uint32_t bd = st + (wn * 32 + pr * 16 + ((lane >> 4) << 3) + (lane & 7)) * ROWB + bcol;
                ldsm_x4(bx[pr], bd + OB_HI);
            }
            #pragma unroll
            for (int mt = 0; mt < 2; mt++)
                #pragma unroll
                for (int nt = 0; nt < 4; nt++) {
                    const uint32_t* bp = &bx[nt >> 1][(nt & 1) * 2];
                    mma_bf16(acc[mt][nt], ah[mt], bp);
                    mma_bf16(acc[mt][nt], al[mt], bp);
                }
            #pragma unroll
            for (int pr = 0; pr < 2; pr++) {
                uint32_t bd = st + (wn * 32 + pr * 16 + ((lane >> 4) << 3) + (lane & 7)) * ROWB + bcol;
                ldsm_x4(bx[pr], bd + OB_LO);
            }
            #pragma unroll
            for (int mt = 0; mt < 2; mt++)
                #pragma unroll
                for (int nt = 0; nt < 4; nt++) {
                    const uint32_t* bp = &bx[nt >> 1][(nt & 1) * 2];
                    mma_bf16(acc[mt][nt], ah[mt], bp);
                }
        }
        __syncthreads();
    }

    if (MODE == EPI_RELU_SPLIT) {
        #pragma unroll
        for (int mt = 0; mt < 2; mt++) {
            #pragma unroll
            for (int half = 0; half < 2; half++) {
                const int mloc = wm * 32 + mt * 16 + half * 8 + (lane >> 2);
                #pragma unroll
                for (int nt = 0; nt < 4; nt++) {
                    const int c0 = nb * 128 + wn * 32 + nt * 8 + (lane & 3) * 2;
                    float v0 = fmaxf(acc[mt][nt][half * 2 + 0] + bias[c0], 0.f);
                    float v1 = fmaxf(acc[mt][nt][half * 2 + 1] + bias[c0 + 1], 0.f);
                    size_t base = (size_t)(mtile * 128 + mloc) * N + c0;
                    bf16 h0 = __float2bfloat16(v0), h1 = __float2bfloat16(v1);
                    outhi[base] = h0; outhi[base + 1] = h1;
                    outlo[base] = __float2bfloat16(v0 - __bfloat162float(h0));
                    outlo[base + 1] = __float2bfloat16(v1 - __bfloat162float(h1));
                }
            }
        }
    } else {
        float p[4][8] = {};
        #pragma unroll
        for (int mt = 0; mt < 2; mt++)
            #pragma unroll
            for (int half = 0; half < 2; half++) {
                const int r = mt * 2 + half;
                #pragma unroll
                for (int nt = 0; nt < 4; nt++)
                    #pragma unroll
                    for (int j = 0; j < 2; j++) {
                        const int cl = wn * 32 + nt * 8 + (lane & 3) * 2 + j;
                        const int c0 = nb * 128 + cl;
                        float v = fmaxf(acc[mt][nt][half * 2 + j] + bias[c0], 0.f);
                        float4 ga = ((const float4*)(s_g3 + c0 * NE))[0];
                        float4 gb = ((const float4*)(s_g3 + c0 * NE))[1];
                        p[r][0] = fmaf(v, ga.x, p[r][0]);
                        p[r][1] = fmaf(v, ga.y, p[r][1]);
                        p[r][2] = fmaf(v, ga.z, p[r][2]);
                        p[r][3] = fmaf(v, ga.w, p[r][3]);
                        p[r][4] = fmaf(v, gb.x, p[r][4]);
                        p[r][5] = fmaf(v, gb.y, p[r][5]);
                        p[r][6] = fmaf(v, gb.z, p[r][6]);
                        p[r][7] = fmaf(v, gb.w, p[r][7]);
                    }
            }
        #pragma unroll
        for (int r = 0; r < 4; r++)
            #pragma unroll
            for (int e = 0; e < NE; e++) {
                p[r][e] += __shfl_xor_sync(0xffffffffu, p[r][e], 1);
                p[r][e] += __shfl_xor_sync(0xffffffffu, p[r][e], 2);
            }
        if ((lane & 3) == 0) {
            #pragma unroll
            for (int r = 0; r < 4; r++) {
                const int mloc = wm * 32 + (r >> 1) * 16 + (r & 1) * 8 + (lane >> 2);
                const int tok = mtile * 128 + mloc;
                #pragma unroll
                for (int e = 0; e < NE; e++)
                    atomicAdd(&g_logit[tok * NE + e], p[r][e]);
            }
        }
    }
}

// ========== plain fp16 GEMM (expert), 3-stage WAIT1, occ 2 ===================
#define HROWB     144
#define HSTAGE_SZ 36864
#define HNSTAGE   3
#define HOA 0
#define HOB 18432
#define SMEM_HGEMM (TILES_OFF + HNSTAGE * HSTAGE_SZ)   // 112640

__global__ void __launch_bounds__(512, 2) h_gemm(
    const __half* __restrict__ A,
    const __half* __restrict__ W,
    const float* __restrict__ bias,
    __half* __restrict__ outh, int N, int K) {
    extern __shared__ char smem[];
    int* s_pid = (int*)smem;
    int* s_tok = (int*)(smem + 512);
    const int tid = threadIdx.x, lane = tid & 31, wid = tid >> 5;
    const int wm = wid >> 2, wn = wid & 3;
    const int nb = blockIdx.x;

    int mtile = blockIdx.y, e = 0;
    {
        int flat = blockIdx.y, base = 0, cnt = 0;
        bool found = false;
        #pragma unroll
        for (int i = 0; i < NE; i++) {
            int c = g_cnt[i];
            int tiles = (c + 127) >> 7;
            if (!found && flat < base + tiles) { e = i; mtile = flat - base; cnt = c; found = true; }
            base += tiles;
        }
        if (!found) return;
        if (tid < 128) {
            int idx = mtile * 128 + tid;
            int pid = (idx < cnt) ? g_list[e * NT + idx] : -1;
            s_pid[tid] = pid;
            s_tok[tid] = (pid >= 0) ? (pid >> 1) : 0;
        }
        W += (size_t)e * HH * DD;
        bias += (size_t)e * HH;
        __syncthreads();
    }

    const uint32_t sb = smem_u32(smem) + TILES_OFF;

    const int seg = tid & 3;
    const int row = tid >> 2;
    size_t arow = (size_t)s_tok[row];
    size_t brow = (size_t)nb * 128 + row;
    const __half* pA = A + arow * K + seg * 8;
    const __half* pB = W + brow * K + seg * 8;
    const uint32_t so = row * HROWB + seg * 16;

    float acc[2][4][4] = {};
    const int niter = K >> 6;

    #pragma unroll
    for (int s = 0; s < 2; s++) {
        if (s < niter) {
            const uint32_t st = sb + s * HSTAGE_SZ;
            const int ko = s << 6;
            cp16(st + HOA + so,      pA + ko);
            cp16(st + HOA + so + 64, pA + ko + 32);
            cp16(st + HOB + so,      pB + ko);
            cp16(st + HOB + so + 64, pB + ko + 32);
        }
        CP_COMMIT();
    }

    int cur = 0, nxt2 = 2;
    for (int it = 0; it < niter; it++) {
        CP_WAIT1();
        __syncthreads();
        {
            const int s = it + 2;
            if (s < niter) {
                const uint32_t st = sb + nxt2 * HSTAGE_SZ;
                const int ko = s << 6;
                cp16(st + HOA + so,      pA + ko);
                cp16(st + HOA + so + 64, pA + ko + 32);
                cp16(st + HOB + so,      pB + ko);
                cp16(st + HOB + so + 64, pB + ko + 32);
            }
            CP_COMMIT();
        }

        const uint32_t st = sb + cur * HSTAGE_SZ;
        #pragma unroll
        for (int ks = 0; ks < 4; ks++) {
            uint32_t ah[2][4], bb[2][4];
            const int acol = (ks * 16 + (lane >> 4) * 8) * 2;
            #pragma unroll
            for (int mt = 0; mt < 2; mt++) {
                uint32_t ad = st + (wm * 32 + mt * 16 + (lane & 15)) * HROWB + acol;
                ldsm_x4(ah[mt], ad + HOA);
            }
            const int bcol = (ks * 16 + ((lane >> 3) & 1) * 8) * 2;
            #pragma unroll
            for (int pr = 0; pr < 2; pr++) {
                uint32_t bd = st + (wn * 32 + pr * 16 + ((lane >> 4) << 3) + (lane & 7)) * HROWB + bcol;
                ldsm_x4(bb[pr], bd + HOB);
            }
            #pragma unroll
            for (int mt = 0; mt < 2; mt++)
                #pragma unroll
                for (int nt = 0; nt < 4; nt++) {
                    const uint32_t* bp = &bb[nt >> 1][(nt & 1) * 2];
                    mma_f16(acc[mt][nt], ah[mt], bp);
                }
        }
        cur = (cur == 2) ? 0 : cur + 1;
        nxt2 = (nxt2 == 2) ? 0 : nxt2 + 1;
    }

    #pragma unroll
    for (int mt = 0; mt < 2; mt++) {
        #pragma unroll
        for (int half = 0; half < 2; half++) {
            const int mloc = wm * 32 + mt * 16 + half * 8 + (lane >> 2);
            int pid = s_pid[mloc];
            if (pid < 0) continue;
            #pragma unroll
            for (int nt = 0; nt < 4; nt++) {
                const int c0 = nb * 128 + wn * 32 + nt * 8 + (lane & 3) * 2;
                float v0 = acc[mt][nt][half * 2 + 0] + bias[c0];
                float v1 = acc[mt][nt][half * 2 + 1] + bias[c0 + 1];
                __half2* dst = (__half2*)(outh + (size_t)pid * HH + c0);
                *dst = __floats2half2_rn(v0, v1);
            }
        }
    }
}

// ===== out-proj GEMM with fused combine: A = relu(w0*pair0 + w1*pair1) ======
// 2-stage B cp.async; A via LDG-prefetch -> combine -> STS, pipelined 1 iter.
#define CSTAGE_SZ 36864
#define COA 0
#define COB 18432
#define SMEM_CGEMM (TILES_OFF + 2 * CSTAGE_SZ)   // 75776

__global__ void __launch_bounds__(512, 2) c_gemm(
    const __half* __restrict__ pair,
    const float* __restrict__ wval,
    const __half* __restrict__ W,
    const float* __restrict__ bias,
    float* __restrict__ outf, int N, int K) {
    extern __shared__ char smem[];
    const int tid = threadIdx.x, lane = tid & 31, wid = tid >> 5;
    const int wm = wid >> 2, wn = wid & 3;
    const int nb = blockIdx.x;
    const int mtile = blockIdx.y;

    const uint32_t sb = smem_u32(smem) + TILES_OFF;
    char* smem_b = smem + TILES_OFF;

    const int seg = tid & 3;
    const int row = tid >> 2;
    const int tok = mtile * 128 + row;
    const float w0 = wval[2 * tok];
    const float w1 = wval[2 * tok + 1];
    size_t brow = (size_t)nb * 128 + row;
    const __half* pa = pair + (size_t)(2 * tok) * K + seg * 8;   // pair row 2t
    const __half* pb2 = pa + K;                                  // pair row 2t+1
    const __half* pB = W + brow * K + seg * 8;
    const uint32_t so = row * HROWB + seg * 16;

    float acc[2][4][4] = {};
    const int niter = K >> 6;   // 32

    // prologue: LDG A(0) into regs; cp.async B(0)
    uint4 ra0 = *(const uint4*)(pa);
    uint4 ra1 = *(const uint4*)(pa + 32);
    uint4 rb0 = *(const uint4*)(pb2);
    uint4 rb1 = *(const uint4*)(pb2 + 32);
    cp16(sb + COB + so,      pB);
    cp16(sb + COB + so + 64, pB + 32);
    CP_COMMIT();

    for (int it = 0; it < niter; it++) {
        CP_WAIT0();                 // B(it) ready
        // combine + STS A(it) into buffer it&1
        {
            char* st = smem_b + (it & 1) * CSTAGE_SZ;
            *(uint4*)(st + COA + so)      = comb16s(ra0, rb0, w0, w1);
            *(uint4*)(st + COA + so + 64) = comb16s(ra1, rb1, w0, w1);
        }
        __syncthreads();            // all threads done with compute(it-1) and STS(it)
        {
            const int s = it + 1;
            if (s < niter) {
                const uint32_t stb = sb + (s & 1) * CSTAGE_SZ;
                const int ko = s << 6;
                cp16(stb + COB + so,      pB + ko);
                cp16(stb + COB + so + 64, pB + ko + 32);
                // prefetch A(it+1) into regs (regs free after STS)
                ra0 = *(const uint4*)(pa + ko);
                ra1 = *(const uint4*)(pa + ko + 32);
                rb0 = *(const uint4*)(pb2 + ko);
                rb1 = *(const uint4*)(pb2 + ko + 32);
            }
            CP_COMMIT();
        }

        const uint32_t st = sb + (it & 1) * CSTAGE_SZ;
        #pragma unroll
        for (int ks = 0; ks < 4; ks++) {
            uint32_t ah[2][4], bb[2][4];
            const int acol = (ks * 16 + (lane >> 4) * 8) * 2;
            #pragma unroll
            for (int mt = 0; mt < 2; mt++) {
                uint32_t ad = st + (wm * 32 + mt * 16 + (lane & 15)) * HROWB + acol;
                ldsm_x4(ah[mt], ad + COA);
            }
            const int bcol = (ks * 16 + ((lane >> 3) & 1) * 8) * 2;
            #pragma unroll
            for (int pr = 0; pr < 2; pr++) {
                uint32_t bd = st + (wn * 32 + pr * 16 + ((lane >> 4) << 3) + (lane & 7)) * HROWB + bcol;
                ldsm_x4(bb[pr], bd + COB);
            }
            #pragma unroll
            for (int mt = 0; mt < 2; mt++)
                #pragma unroll
                for (int nt = 0; nt < 4; nt++) {
                    const uint32_t* bp = &bb[nt >> 1][(nt & 1) * 2];
                    mma_f16(acc[mt][nt], ah[mt], bp);
                }
        }
        __syncthreads();            // compute(it) done before STS(it+1)/cp B(it+2) reuse
    }

    #pragma unroll
    for (int mt = 0; mt < 2; mt++) {
        #pragma unroll
        for (int half = 0; half < 2; half++) {
            const int mloc = wm * 32 + mt * 16 + half * 8 + (lane >> 2);
            #pragma unroll
            for (int nt = 0; nt < 4; nt++) {
                const int c0 = nb * 128 + wn * 32 + nt * 8 + (lane & 3) * 2;
                float v0 = acc[mt][nt][half * 2 + 0] + bias[c0];
                float v1 = acc[mt][nt][half * 2 + 1] + bias[c0 + 1];
                size_t base = (size_t)(mtile * 128 + mloc) * N + c0;
                outf[base] = v0; outf[base + 1] = v1;
            }
        }
    }
}

// ---------------- launch ------------------------------------------------------
extern "C" void kernel_launch(void* const* d_in, const int* in_sizes, int n_in,
                              void* d_out, int out_size) {
    const float* x    = (const float*)d_in[0];
    const int*   ft   = (const int*)  d_in[1];
    const float* gw1  = (const float*)d_in[2];
    const float* gb1  = (const float*)d_in[3];
    const float* gw2  = (const float*)d_in[4];
    const float* gb2  = (const float*)d_in[5];
    const float* gw3  = (const float*)d_in[6];
    const float* gb3  = (const float*)d_in[7];
    const float* temb = (const float*)d_in[8];
    const float* tw   = (const float*)d_in[9];
    const float* tb   = (const float*)d_in[10];
    const float* ew   = (const float*)d_in[11];
    const float* eb   = (const float*)d_in[12];
    const float* ow   = (const float*)d_in[13];
    const float* ob   = (const float*)d_in[14];
    float* out = (float*)d_out;

    bf16 *xhi, *xlo, *h1hi, *h1lo, *w1hi, *w1lo, *w2hi, *w2lo;
    __half *xh, *ewh, *owh, *pairh;
    float *wvalp;
    cudaGetSymbolAddress((void**)&xhi, g_xhi);   cudaGetSymbolAddress((void**)&xlo, g_xlo);
    cudaGetSymbolAddress((void**)&h1hi, g_h1hi); cudaGetSymbolAddress((void**)&h1lo, g_h1lo);
    cudaGetSymbolAddress((void**)&w1hi, g_w1hi); cudaGetSymbolAddress((void**)&w1lo, g_w1lo);
    cudaGetSymbolAddress((void**)&w2hi, g_w2hi); cudaGetSymbolAddress((void**)&w2lo, g_w2lo);
    cudaGetSymbolAddress((void**)&xh, g_xh);
    cudaGetSymbolAddress((void**)&ewh, g_ewh);   cudaGetSymbolAddress((void**)&owh, g_owh);
    cudaGetSymbolAddress((void**)&pairh, g_pairh);
    cudaGetSymbolAddress((void**)&wvalp, g_wval);

    cudaFuncSetAttribute(mma_gemm<EPI_RELU_SPLIT>, cudaFuncAttributeMaxDynamicSharedMemorySize, SMEM_GEMM);
    cudaFuncSetAttribute(mma_gemm<EPI_GATE>,       cudaFuncAttributeMaxDynamicSharedMemorySize, SMEM_GATE);
    cudaFuncSetAttribute(h_gemm, cudaFuncAttributeMaxDynamicSharedMemorySize, SMEM_HGEMM);
    cudaFuncSetAttribute(c_gemm, cudaFuncAttributeMaxDynamicSharedMemorySize, SMEM_CGEMM);

    // fused conversions + counter/logit zeroing + tb3 table
    prep_kernel<<<PREP_BLOCKS, 256>>>(x, gw1, gw2, ew, ow, gb3, temb, tw, tb);

    // gating layer 1 (bf16 3-term) -> h1 split
    mma_gemm<EPI_RELU_SPLIT><<<dim3(GHA / 128, NT / 128), 512, SMEM_GEMM>>>(
        xhi, xlo, w1hi, w1lo, gb1, nullptr, h1hi, h1lo, GHA, DD);

    // gating layer 2 (bf16 3-term) + fused logit projection -> g_logit
    mma_gemm<EPI_GATE><<<dim3(GHB / 128, NT / 128), 512, SMEM_GATE>>>(
        h1hi, h1lo, w2hi, w2lo, gb2, gw3, nullptr, nullptr, GHB, GHA);

    // routing: precomputed tb3 + top2 + two-level atomics
    routing_kernel<<<NT / 256, 256>>>(ft);

    // expert grouped GEMM (fp16, gathered A, scattered fp16 C)
    h_gemm<<<dim3(HH / 128, MAX_MTILES), 512, SMEM_HGEMM>>>(
        xh, ewh, eb, pairh, HH, DD);

    // output projection with fused combine (reads pairh + wval directly)
    c_gemm<<<dim3(DD / 128, NT / 128), 512, SMEM_CGEMM>>>(
        pairh, wvalp, owh, ob, out, DD, HH);
}

// round 16
// speedup vs baseline: 1.1309x; 1.1309x over previous
#include <cuda_runtime.h>
#include <cuda_bf16.h>
#include <cuda_fp16.h>
#include <cstdint>

#define NT   8192
#define DD   1024
#define GHA  512
#define GHB  256
#define NE   8
#define HH   2048
#define MAX_MTILES 136

typedef __nv_bfloat16 bf16;

// ---------------- scratch ---------------------------------------------------
__device__ bf16  g_xhi[NT * DD],  g_xlo[NT * DD];
__device__ bf16  g_h1hi[NT * GHA], g_h1lo[NT * GHA];
__device__ bf16  g_w1hi[GHA * DD], g_w1lo[GHA * DD];
__device__ bf16  g_w2hi[GHB * GHA], g_w2lo[GHB * GHA];
__device__ __half g_xh[NT * DD];
__device__ __half g_ewh[(size_t)NE * HH * DD];             // [E][H][D]
__device__ __half g_owh[(size_t)DD * HH];                  // [D][H]
__device__ __half g_mh[(size_t)NT * HH];
__device__ __half g_pairh[(size_t)NT * 2 * HH];
__device__ float g_logit[NT * NE];
__device__ float g_tb3[3 * NE];
__device__ float g_wval[NT * 2];
__device__ int   g_cnt[NE];
__device__ int   g_list[NE * NT];

// ---------------- PTX helpers (sm_80+ baseline only) ------------------------
__device__ __forceinline__ uint32_t smem_u32(const void* p) {
    uint32_t a;
    asm("{ .reg .u64 t; cvta.to.shared.u64 t, %1; cvt.u32.u64 %0, t; }" : "=r"(a) : "l"(p));
    return a;
}
__device__ __forceinline__ void cp16(uint32_t s, const void* g) {
    asm volatile("cp.async.cg.shared.global [%0], [%1], 16;" :: "r"(s), "l"(g));
}
#define CP_COMMIT() asm volatile("cp.async.commit_group;" ::: "memory")
#define CP_WAIT1()  asm volatile("cp.async.wait_group 1;" ::: "memory")
#define CP_WAIT0()  asm volatile("cp.async.wait_group 0;" ::: "memory")

__device__ __forceinline__ void ldsm_x4(uint32_t* r, uint32_t a) {
    asm volatile("ldmatrix.sync.aligned.m8n8.x4.shared.b16 {%0,%1,%2,%3}, [%4];"
        : "=r"(r[0]), "=r"(r[1]), "=r"(r[2]), "=r"(r[3]) : "r"(a));
}
__device__ __forceinline__ void mma_bf16(float* c, const uint32_t* a, const uint32_t* b) {
    asm volatile("mma.sync.aligned.m16n8k16.row.col.f32.bf16.bf16.f32 "
        "{%0,%1,%2,%3}, {%4,%5,%6,%7}, {%8,%9}, {%0,%1,%2,%3};"
        : "+f"(c[0]), "+f"(c[1]), "+f"(c[2]), "+f"(c[3])
        : "r"(a[0]), "r"(a[1]), "r"(a[2]), "r"(a[3]), "r"(b[0]), "r"(b[1]));
}
__device__ __forceinline__ void mma_f16(float* c, const uint32_t* a, const uint32_t* b) {
    asm volatile("mma.sync.aligned.m16n8k16.row.col.f32.f16.f16.f32 "
        "{%0,%1,%2,%3}, {%4,%5,%6,%7}, {%8,%9}, {%0,%1,%2,%3};"
        : "+f"(c[0]), "+f"(c[1]), "+f"(c[2]), "+f"(c[3])
        : "r"(a[0]), "r"(a[1]), "r"(a[2]), "r"(a[3]), "r"(b[0]), "r"(b[1]));
}

// combine 8 halves: relu(w0*a + w1*b) -> fp16 (identical math to old combine)
__device__ __forceinline__ uint4 comb16s(uint4 a, uint4 b, float w0, float w1) {
    uint4 o;
    const uint32_t* ap = (const uint32_t*)&a;
    const uint32_t* bp = (const uint32_t*)&b;
    __half2* op = (__half2*)&o;
    #pragma unroll
    for (int i = 0; i < 4; i++) {
        float2 fa = __half22float2(*(const __half2*)&ap[i]);
        float2 fb = __half22float2(*(const __half2*)&bp[i]);
        float v0 = fmaxf(fmaf(w0, fa.x, w1 * fb.x), 0.f);
        float v1 = fmaxf(fmaf(w0, fa.y, w1 * fb.y), 0.f);
        op[i] = __floats2half2_rn(v0, v1);
    }
    return o;
}

// ---------------- fused prep kernel ------------------------------------------
#define PREP_BLOCKS 27265

__global__ void __launch_bounds__(256) prep_kernel(
    const float* __restrict__ x, const float* __restrict__ gw1,
    const float* __restrict__ gw2, const float* __restrict__ ew,
    const float* __restrict__ ow,
    const float* __restrict__ gb3, const float* __restrict__ temb,
    const float* __restrict__ tw, const float* __restrict__ tb) {
    __shared__ float t[32][33];
    int b = blockIdx.x;
    const int tid = threadIdx.x;

    if (b == PREP_BLOCKS - 1) {
        if (tid < 192) {
            const int p = tid >> 3;
            const int s = tid & 7;
            const int ty = p / NE, e = p % NE;
            float sum = 0.f;
            #pragma unroll
            for (int k = 0; k < 16; k++) {
                int j = s + (k << 3);
                sum += temb[ty * 128 + j] * tw[j * NE + e];
            }
            #pragma unroll
            for (int off = 4; off; off >>= 1)
                sum += __shfl_down_sync(0xffffffffu, sum, off);
            if (s == 0) g_tb3[p] = sum + gb3[e] + tb[e];
        }
        return;
    }

    if (b < 8192) {
        if (b == 0 && tid < NE) g_cnt[tid] = 0;
        if (b < 64) {
            ((float4*)g_logit)[b * 256 + tid] = make_float4(0.f, 0.f, 0.f, 0.f);
        }
        int i4 = b * 256 + tid;
        float4 v = ((const float4*)x)[i4];
        float f[4] = {v.x, v.y, v.z, v.w};
        bf16 bh[4]; bf16 bl[4]; __half hh[4];
        #pragma unroll
        for (int k = 0; k < 4; k++) {
            bh[k] = __float2bfloat16(f[k]);
            bl[k] = __float2bfloat16(f[k] - __bfloat162float(bh[k]));
            hh[k] = __float2half(f[k]);
        }
        __nv_bfloat162* xhi2 = (__nv_bfloat162*)g_xhi;
        __nv_bfloat162* xlo2 = (__nv_bfloat162*)g_xlo;
        __half2* xh2 = (__half2*)g_xh;
        xhi2[2 * i4 + 0] = __nv_bfloat162(bh[0], bh[1]);
        xhi2[2 * i4 + 1] = __nv_bfloat162(bh[2], bh[3]);
        xlo2[2 * i4 + 0] = __nv_bfloat162(bl[0], bl[1]);
        xlo2[2 * i4 + 1] = __nv_bfloat162(bl[2], bl[3]);
        xh2[2 * i4 + 0] = __half2(hh[0], hh[1]);
        xh2[2 * i4 + 1] = __half2(hh[2], hh[3]);
        return;
    }
    b -= 8192;

    const float* in;
    bf16 *ohi = nullptr, *olo = nullptr;
    __half* oh = nullptr;
    int R, C, bx, by;
    size_t zoff = 0;
    bool half_mode;
    if (b < 512) {
        half_mode = false; in = gw1; ohi = g_w1hi; olo = g_w1lo;
        R = DD; C = GHA; bx = b % 16; by = b / 16;
    } else if (b < 640) {
        b -= 512;
        half_mode = false; in = gw2; ohi = g_w2hi; olo = g_w2lo;
        R = GHA; C = GHB; bx = b % 8; by = b / 8;
    } else if (b < 640 + 16384) {
        b -= 640;
        half_mode = true; in = ew; oh = g_ewh;
        R = DD; C = HH; bx = b % 64; by = (b / 64) % 32;
        zoff = (size_t)(b / (64 * 32)) * R * C;
    } else {
        b -= 640 + 16384;
        half_mode = true; in = ow; oh = g_owh;
        R = HH; C = DD; bx = b % 32; by = b / 32;
    }
    in += zoff;
    const int c0 = bx * 32, r0 = by * 32;
    const int tx = tid & 31, ty = tid >> 5;
    for (int i = ty; i < 32; i += 8)
        t[i][tx] = in[(size_t)(r0 + i) * C + c0 + tx];
    __syncthreads();
    if (half_mode) {
        oh += zoff;
        for (int i = ty; i < 32; i += 8)
            oh[(size_t)(c0 + i) * R + r0 + tx] = __float2half(t[tx][i]);
    } else {
        for (int i = ty; i < 32; i += 8) {
            float v = t[tx][i];
            bf16 h = __float2bfloat16(v);
            size_t o = (size_t)(c0 + i) * R + r0 + tx;
            ohi[o] = h;
            olo[o] = __float2bfloat16(v - __bfloat162float(h));
        }
    }
}

// ---------------- routing: two-level atomics ---------------------------------
__global__ void __launch_bounds__(256) routing_kernel(const int* __restrict__ ftypes) {
    __shared__ float s_tb3[3 * NE];
    __shared__ int s_cnt[NE];
    __shared__ int s_base[NE];
    const int tid = threadIdx.x;
    if (tid < 3 * NE) s_tb3[tid] = g_tb3[tid];
    if (tid < NE) s_cnt[tid] = 0;
    __syncthreads();
    const int t = blockIdx.x * 256 + tid;
    float4 l0 = ((const float4*)g_logit)[t * 2 + 0];
    float4 l1 = ((const float4*)g_logit)[t * 2 + 1];
    float logits[NE] = {l0.x, l0.y, l0.z, l0.w, l1.x, l1.y, l1.z, l1.w};
    int ftv = ftypes[t];
    #pragma unroll
    for (int e = 0; e < NE; e++) logits[e] += s_tb3[ftv * NE + e];
    int i0 = 0;
    #pragma unroll
    for (int e = 1; e < NE; e++) if (logits[e] > logits[i0]) i0 = e;
    int i1 = (i0 == 0) ? 1 : 0;
    #pragma unroll
    for (int e = 0; e < NE; e++) {
        if (e == i0 || e == i1) continue;
        if (logits[e] > logits[i1]) i1 = e;
    }
    float r = expf(logits[i1] - logits[i0]);
    float inv = 1.f / (1.f + r);
    g_wval[t * 2 + 0] = inv;
    g_wval[t * 2 + 1] = r * inv;
    int p0 = atomicAdd(&s_cnt[i0], 1);
    int p1 = atomicAdd(&s_cnt[i1], 1);
    __syncthreads();
    if (tid < NE) s_base[tid] = atomicAdd(&g_cnt[tid], s_cnt[tid]);
    __syncthreads();
    g_list[i0 * NT + s_base[i0] + p0] = t * 2 + 0;
    g_list[i1 * NT + s_base[i1] + p1] = t * 2 + 1;
}

// ================= bf16 3-term GEMM (gating), 2-stage, occ 2 =================
#define EPI_RELU_SPLIT 0
#define EPI_GATE       1

#define ROWB      80
#define TILES_OFF 2048
#define STAGE_SZ  40960
#define OA_HI 0
#define OA_LO 10240
#define OB_HI 20480
#define OB_LO 30720
#define GATE_OFF  (TILES_OFF + 2 * STAGE_SZ)
#define SMEM_GEMM GATE_OFF                       // 83968
#define SMEM_GATE (GATE_OFF + GHB * NE * 4)      // 92160

template<int MODE>
__global__ void __launch_bounds__(512, 2) mma_gemm(
    const bf16* __restrict__ Ahi, const bf16* __restrict__ Alo,
    const bf16* __restrict__ Bhi, const bf16* __restrict__ Blo,
    const float* __restrict__ bias, const float* __restrict__ gw3,
    bf16* __restrict__ outhi, bf16* __restrict__ outlo,
    int N, int K) {
    extern __shared__ char smem[];
    const int tid = threadIdx.x, lane = tid & 31, wid = tid >> 5;
    const int wm = wid >> 2, wn = wid & 3;
    const int nb = blockIdx.x;
    const int mtile = blockIdx.y;

    float* s_g3 = (float*)(smem + GATE_OFF);
    if (MODE == EPI_GATE) {
        for (int i = tid; i < GHB * NE; i += 512) s_g3[i] = gw3[i];
    }

    const uint32_t sb = smem_u32(smem) + TILES_OFF;

    const int seg = tid & 3;
    const int row = tid >> 2;
    size_t arow = (size_t)mtile * 128 + row;
    size_t brow = (size_t)nb * 128 + row;
    const bf16* pAh = Ahi + arow * K + seg * 8;
    const bf16* pAl = Alo + arow * K + seg * 8;
    const bf16* pBh = Bhi + brow * K + seg * 8;
    const bf16* pBl = Blo + brow * K + seg * 8;
    const uint32_t so = row * ROWB + seg * 16;

    float acc[2][4][4] = {};
    const int niter = K >> 5;

    {
        cp16(sb + OA_HI + so, pAh);
        cp16(sb + OA_LO + so, pAl);
        cp16(sb + OB_HI + so, pBh);
        cp16(sb + OB_LO + so, pBl);
        CP_COMMIT();
    }

    for (int it = 0; it < niter; it++) {
        CP_WAIT0();
        __syncthreads();
        {
            const int s = it + 1;
            if (s < niter) {
                const uint32_t st = sb + (s & 1) * STAGE_SZ;
                const int ko = s << 5;
                cp16(st + OA_HI + so, pAh + ko);
                cp16(st + OA_LO + so, pAl + ko);
                cp16(st + OB_HI + so, pBh + ko);
                cp16(st + OB_LO + so, pBl + ko);
            }
            CP_COMMIT();
        }

        const uint32_t st = sb + (it & 1) * STAGE_SZ;
        #pragma unroll
        for (int ks = 0; ks < 2; ks++) {
            uint32_t ah[2][4], al[2][4], bx[2][4];
            const int acol = (ks * 16 + (lane >> 4) * 8) * 2;
            #pragma unroll
            for (int mt = 0; mt < 2; mt++) {
                uint32_t ad = st + (wm * 32 + mt * 16 + (lane & 15)) * ROWB + acol;
                ldsm_x4(ah[mt], ad + OA_HI);
                ldsm_x4(al[mt], ad + OA_LO);
            }
            const int bcol = (ks * 16 + ((lane >> 3) & 1) * 8) * 2;
            #pragma unroll
            for (int pr = 0; pr < 2; pr++) {
                uint32_t bd = st + (wn * 32 + pr * 16 + ((lane >> 4) << 3) + (lane & 7)) * ROWB + bcol;
                ldsm_x4(bx[pr], bd + OB_HI);
            }
            #pragma unroll
            for (int mt = 0; mt < 2; mt++)
                #pragma unroll
                for (int nt = 0; nt < 4; nt++) {
                    const uint32_t* bp = &bx[nt >> 1][(nt & 1) * 2];
                    mma_bf16(acc[mt][nt], ah[mt], bp);
                    mma_bf16(acc[mt][nt], al[mt], bp);
                }
            #pragma unroll
            for (int pr = 0; pr < 2; pr++) {
                uint32_t bd = st + (wn * 32 + pr * 16 + ((lane >> 4) << 3) + (lane & 7)) * ROWB + bcol;
                ldsm_x4(bx[pr], bd + OB_LO);
            }
            #pragma unroll
            for (int mt = 0; mt < 2; mt++)
                #pragma unroll
                for (int nt = 0; nt < 4; nt++) {
                    const uint32_t* bp = &bx[nt >> 1][(nt & 1) * 2];
                    mma_bf16(acc[mt][nt], ah[mt], bp);
                }
        }
        __syncthreads();
    }

    if (MODE == EPI_RELU_SPLIT) {
        #pragma unroll
        for (int mt = 0; mt < 2; mt++) {
            #pragma unroll
            for (int half = 0; half < 2; half++) {
                const int mloc = wm * 32 + mt * 16 + half * 8 + (lane >> 2);
                #pragma unroll
                for (int nt = 0; nt < 4; nt++) {
                    const int c0 = nb * 128 + wn * 32 + nt * 8 + (lane & 3) * 2;
                    float v0 = fmaxf(acc[mt][nt][half * 2 + 0] + bias[c0], 0.f);
                    float v1 = fmaxf(acc[mt][nt][half * 2 + 1] + bias[c0 + 1], 0.f);
                    size_t base = (size_t)(mtile * 128 + mloc) * N + c0;
                    bf16 h0 = __float2bfloat16(v0), h1 = __float2bfloat16(v1);
                    outhi[base] = h0; outhi[base + 1] = h1;
                    outlo[base] = __float2bfloat16(v0 - __bfloat162float(h0));
                    outlo[base + 1] = __float2bfloat16(v1 - __bfloat162float(h1));
                }
            }
        }
    } else {
        float p[4][8] = {};
        #pragma unroll
        for (int mt = 0; mt < 2; mt++)
            #pragma unroll
            for (int half = 0; half < 2; half++) {
                const int r = mt * 2 + half;
                #pragma unroll
                for (int nt = 0; nt < 4; nt++)
                    #pragma unroll
                    for (int j = 0; j < 2; j++) {
                        const int cl = wn * 32 + nt * 8 + (lane & 3) * 2 + j;
                        const int c0 = nb * 128 + cl;
                        float v = fmaxf(acc[mt][nt][half * 2 + j] + bias[c0], 0.f);
                        float4 ga = ((const float4*)(s_g3 + c0 * NE))[0];
                        float4 gb = ((const float4*)(s_g3 + c0 * NE))[1];
                        p[r][0] = fmaf(v, ga.x, p[r][0]);
                        p[r][1] = fmaf(v, ga.y, p[r][1]);
                        p[r][2] = fmaf(v, ga.z, p[r][2]);
                        p[r][3] = fmaf(v, ga.w, p[r][3]);
                        p[r][4] = fmaf(v, gb.x, p[r][4]);
                        p[r][5] = fmaf(v, gb.y, p[r][5]);
                        p[r][6] = fmaf(v, gb.z, p[r][6]);
                        p[r][7] = fmaf(v, gb.w, p[r][7]);
                    }
            }
        #pragma unroll
        for (int r = 0; r < 4; r++)
            #pragma unroll
            for (int e = 0; e < NE; e++) {
                p[r][e] += __shfl_xor_sync(0xffffffffu, p[r][e], 1);
                p[r][e] += __shfl_xor_sync(0xffffffffu, p[r][e], 2);
            }
        if ((lane & 3) == 0) {
            #pragma unroll
            for (int r = 0; r < 4; r++) {
                const int mloc = wm * 32 + (r >> 1) * 16 + (r & 1) * 8 + (lane >> 2);
                const int tok = mtile * 128 + mloc;
                #pragma unroll
                for (int e = 0; e < NE; e++)
                    atomicAdd(&g_logit[tok * NE + e], p[r][e]);
            }
        }
    }
}

// ========== plain fp16 GEMM (expert + outproj), 3-stage WAIT1, occ 2 =========
#define HEPI_SCATTER 0
#define HEPI_F32     1

#define HROWB     144
#define HSTAGE_SZ 36864
#define HNSTAGE   3
#define HOA 0
#define HOB 18432
#define SMEM_HGEMM (TILES_OFF + HNSTAGE * HSTAGE_SZ)   // 112640

template<int MODE, bool GATHER>
__global__ void __launch_bounds__(512, 2) h_gemm(
    const __half* __restrict__ A,
    const __half* __restrict__ W,
    const float* __restrict__ bias,
    float* __restrict__ outf, __half* __restrict__ outh, int N, int K) {
    extern __shared__ char smem[];
    int* s_pid = (int*)smem;
    int* s_tok = (int*)(smem + 512);
    const int tid = threadIdx.x, lane = tid & 31, wid = tid >> 5;
    const int wm = wid >> 2, wn = wid & 3;
    const int nb = blockIdx.x;

    int mtile = blockIdx.y, e = 0;
    if (GATHER) {
        int flat = blockIdx.y, base = 0, cnt = 0;
        bool found = false;
        #pragma unroll
        for (int i = 0; i < NE; i++) {
            int c = g_cnt[i];
            int tiles = (c + 127) >> 7;
            if (!found && flat < base + tiles) { e = i; mtile = flat - base; cnt = c; found = true; }
            base += tiles;
        }
        if (!found) return;
        if (tid < 128) {
            int idx = mtile * 128 + tid;
            int pid = (idx < cnt) ? g_list[e * NT + idx] : -1;
            s_pid[tid] = pid;
            s_tok[tid] = (pid >= 0) ? (pid >> 1) : 0;
        }
        W += (size_t)e * HH * DD;
        bias += (size_t)e * HH;
        __syncthreads();
    }

    const uint32_t sb = smem_u32(smem) + TILES_OFF;

    const int seg = tid & 3;
    const int row = tid >> 2;
    size_t arow = GATHER ? (size_t)s_tok[row] : ((size_t)mtile * 128 + row);
    size_t brow = (size_t)nb * 128 + row;
    const __half* pA = A + arow * K + seg * 8;
    const __half* pB = W + brow * K + seg * 8;
    const uint32_t so = row * HROWB + seg * 16;

    float acc[2][4][4] = {};
    const int niter = K >> 6;

    #pragma unroll
    for (int s = 0; s < 2; s++) {
        if (s < niter) {
            const uint32_t st = sb + s * HSTAGE_SZ;
            const int ko = s << 6;
            cp16(st + HOA + so,      pA + ko);
            cp16(st + HOA + so + 64, pA + ko + 32);
            cp16(st + HOB + so,      pB + ko);
            cp16(st + HOB + so + 64, pB + ko + 32);
        }
        CP_COMMIT();
    }

    int cur = 0, nxt2 = 2;
    for (int it = 0; it < niter; it++) {
        CP_WAIT1();
        __syncthreads();
        {
            const int s = it + 2;
            if (s < niter) {
                const uint32_t st = sb + nxt2 * HSTAGE_SZ;
                const int ko = s << 6;
                cp16(st + HOA + so,      pA + ko);
                cp16(st + HOA + so + 64, pA + ko + 32);
                cp16(st + HOB + so,      pB + ko);
                cp16(st + HOB + so + 64, pB + ko + 32);
            }
            CP_COMMIT();
        }

        const uint32_t st = sb + cur * HSTAGE_SZ;
        #pragma unroll
        for (int ks = 0; ks < 4; ks++) {
            uint32_t ah[2][4], bb[2][4];
            const int acol = (ks * 16 + (lane >> 4) * 8) * 2;
            #pragma unroll
            for (int mt = 0; mt < 2; mt++) {
                uint32_t ad = st + (wm * 32 + mt * 16 + (lane & 15)) * HROWB + acol;
                ldsm_x4(ah[mt], ad + HOA);
            }
            const int bcol = (ks * 16 + ((lane >> 3) & 1) * 8) * 2;
            #pragma unroll
            for (int pr = 0; pr < 2; pr++) {
                uint32_t bd = st + (wn * 32 + pr * 16 + ((lane >> 4) << 3) + (lane & 7)) * HROWB + bcol;
                ldsm_x4(bb[pr], bd + HOB);
            }
            #pragma unroll
            for (int mt = 0; mt < 2; mt++)
                #pragma unroll
                for (int nt = 0; nt < 4; nt++) {
                    const uint32_t* bp = &bb[nt >> 1][(nt & 1) * 2];
                    mma_f16(acc[mt][nt], ah[mt], bp);
                }
        }
        cur = (cur == 2) ? 0 : cur + 1;
        nxt2 = (nxt2 == 2) ? 0 : nxt2 + 1;
    }

    #pragma unroll
    for (int mt = 0; mt < 2; mt++) {
        #pragma unroll
        for (int half = 0; half < 2; half++) {
            const int mloc = wm * 32 + mt * 16 + half * 8 + (lane >> 2);
            int pid = 0;
            if (GATHER) { pid = s_pid[mloc]; if (pid < 0) continue; }
            #pragma unroll
            for (int nt = 0; nt < 4; nt++) {
                const int c0 = nb * 128 + wn * 32 + nt * 8 + (lane & 3) * 2;
                float v0 = acc[mt][nt][half * 2 + 0] + bias[c0];
                float v1 = acc[mt][nt][half * 2 + 1] + bias[c0 + 1];
                if (MODE == HEPI_SCATTER) {
                    __half2* dst = (__half2*)(outh + (size_t)pid * HH + c0);
                    *dst = __floats2half2_rn(v0, v1);
                } else {
                    size_t base = (size_t)(mtile * 128 + mloc) * N + c0;
                    outf[base] = v0; outf[base + 1] = v1;
                }
            }
        }
    }
}

// ---------------- combine: moe = relu(w0*p0 + w1*p1) -> fp16 (uint4) ---------
__global__ void combine_kernel() {
    int idx = blockIdx.x * blockDim.x + threadIdx.x;   // over NT*HH/8
    int t = idx >> 8;                                  // HH/8 = 256 uint4/token
    int c = idx & 255;
    float w0 = g_wval[2 * t], w1 = g_wval[2 * t + 1];
    const uint4* p = (const uint4*)g_pairh;            // 256 uint4 per pair row
    uint4 a = p[(size_t)(2 * t) * 256 + c];
    uint4 b = p[(size_t)(2 * t + 1) * 256 + c];
    ((uint4*)g_mh)[idx] = comb16s(a, b, w0, w1);
}

// ---------------- launch ------------------------------------------------------
extern "C" void kernel_launch(void* const* d_in, const int* in_sizes, int n_in,
                              void* d_out, int out_size) {
    const float* x    = (const float*)d_in[0];
    const int*   ft   = (const int*)  d_in[1];
    const float* gw1  = (const float*)d_in[2];
    const float* gb1  = (const float*)d_in[3];
    const float* gw2  = (const float*)d_in[4];
    const float* gb2  = (const float*)d_in[5];
    const float* gw3  = (const float*)d_in[6];
    const float* gb3  = (const float*)d_in[7];
    const float* temb = (const float*)d_in[8];
    const float* tw   = (const float*)d_in[9];
    const float* tb   = (const float*)d_in[10];
    const float* ew   = (const float*)d_in[11];
    const float* eb   = (const float*)d_in[12];
    const float* ow   = (const float*)d_in[13];
    const float* ob   = (const float*)d_in[14];
    float* out = (float*)d_out;

    bf16 *xhi, *xlo, *h1hi, *h1lo, *w1hi, *w1lo, *w2hi, *w2lo;
    __half *xh, *ewh, *owh, *mh, *pairh;
    cudaGetSymbolAddress((void**)&xhi, g_xhi);   cudaGetSymbolAddress((void**)&xlo, g_xlo);
    cudaGetSymbolAddress((void**)&h1hi, g_h1hi); cudaGetSymbolAddress((void**)&h1lo, g_h1lo);
    cudaGetSymbolAddress((void**)&w1hi, g_w1hi); cudaGetSymbolAddress((void**)&w1lo, g_w1lo);
    cudaGetSymbolAddress((void**)&w2hi, g_w2hi); cudaGetSymbolAddress((void**)&w2lo, g_w2lo);
    cudaGetSymbolAddress((void**)&xh, g_xh);
    cudaGetSymbolAddress((void**)&ewh, g_ewh);   cudaGetSymbolAddress((void**)&owh, g_owh);
    cudaGetSymbolAddress((void**)&mh, g_mh);     cudaGetSymbolAddress((void**)&pairh, g_pairh);

    cudaFuncSetAttribute(mma_gemm<EPI_RELU_SPLIT>, cudaFuncAttributeMaxDynamicSharedMemorySize, SMEM_GEMM);
    cudaFuncSetAttribute(mma_gemm<EPI_GATE>,       cudaFuncAttributeMaxDynamicSharedMemorySize, SMEM_GATE);
    cudaFuncSetAttribute(h_gemm<HEPI_SCATTER, true>,  cudaFuncAttributeMaxDynamicSharedMemorySize, SMEM_HGEMM);
    cudaFuncSetAttribute(h_gemm<HEPI_F32,     false>, cudaFuncAttributeMaxDynamicSharedMemorySize, SMEM_HGEMM);

    // fused conversions + counter/logit zeroing + tb3 table
    prep_kernel<<<PREP_BLOCKS, 256>>>(x, gw1, gw2, ew, ow, gb3, temb, tw, tb);

    // gating layer 1 (bf16 3-term) -> h1 split
    mma_gemm<EPI_RELU_SPLIT><<<dim3(GHA / 128, NT / 128), 512, SMEM_GEMM>>>(
        xhi, xlo, w1hi, w1lo, gb1, nullptr, h1hi, h1lo, GHA, DD);

    // gating layer 2 (bf16 3-term) + fused logit projection -> g_logit
    mma_gemm<EPI_GATE><<<dim3(GHB / 128, NT / 128), 512, SMEM_GATE>>>(
        h1hi, h1lo, w2hi, w2lo, gb2, gw3, nullptr, nullptr, GHB, GHA);

    // routing: precomputed tb3 + top2 + two-level atomics
    routing_kernel<<<NT / 256, 256>>>(ft);

    // expert grouped GEMM (fp16, gathered A, scattered fp16 C)
    h_gemm<HEPI_SCATTER, true><<<dim3(HH / 128, MAX_MTILES), 512, SMEM_HGEMM>>>(
        xh, ewh, eb, nullptr, pairh, HH, DD);

    // combine + relu -> fp16
    combine_kernel<<<(NT * HH / 8) / 256, 256>>>();

    // output projection (fp16)
    h_gemm<HEPI_F32, false><<<dim3(DD / 128, NT / 128), 512, SMEM_HGEMM>>>(
        mh, owh, ob, out, nullptr, DD, HH);
}